// round 3
// baseline (speedup 1.0000x reference)
#include <cuda_runtime.h>
#include <cuda_fp16.h>
#include <math.h>

#define N_LABELS 30000
#define HIDDEN   1024
#define BATCH    256
#define N_EDGES  (N_LABELS - 1)

#define BCE_BLOCKS (BATCH / 2)                 // 128 CTAs own 2 batch rows each
#define GRID       148                         // one CTA per SM, single wave
#define NTHREADS   1024
#define SMEM_BYTES (2 * N_LABELS * (int)sizeof(__half))   // 120000 B

// Device globals (no allocation allowed).
__device__ int2     g_edge[N_EDGES];   // packed (parent, child) int32
__device__ double   g_part[GRID][3];   // per-block partials: bce, rec, prob
__device__ unsigned g_ticket;          // final-combine ticket
__device__ unsigned g_work;            // rec edge work-steal counter

// ---------------------------------------------------------------------------
// Init: convert indices (auto-detect int64 vs int32) + reset counters.
// ---------------------------------------------------------------------------
__global__ void init_kernel(const void* __restrict__ par_raw,
                            const void* __restrict__ chi_raw) {
    __shared__ int s_is32;
    if (threadIdx.x == 0) s_is32 = 0;
    __syncthreads();
    if (threadIdx.x < 64) {
        long long v = ((const long long*)par_raw)[threadIdx.x];
        if (v < 0 || v >= (long long)N_LABELS) atomicOr(&s_is32, 1);
    }
    __syncthreads();
    const bool is32 = (s_is32 != 0);

    int i = blockIdx.x * blockDim.x + threadIdx.x;
    if (i < N_EDGES) {
        int p, c;
        if (is32) {
            p = ((const int*)par_raw)[i];
            c = ((const int*)chi_raw)[i];
        } else {
            p = (int)((const long long*)par_raw)[i];
            c = (int)((const long long*)chi_raw)[i];
        }
        g_edge[i] = make_int2(p, c);
    }
    if (blockIdx.x == 0 && threadIdx.x == 0) {
        g_work = 0u;
        g_ticket = 0u;
    }
}

// ---------------------------------------------------------------------------
// Reductions (caller syncs between reuses of the scratch array).
// ---------------------------------------------------------------------------
__device__ __forceinline__ float block_reduce_f(float v, float* red) {
    const int lane = threadIdx.x & 31;
    const int wid  = threadIdx.x >> 5;
#pragma unroll
    for (int o = 16; o; o >>= 1) v += __shfl_down_sync(0xffffffffu, v, o);
    if (lane == 0) red[wid] = v;
    __syncthreads();
    float r = 0.f;
    if (wid == 0) {
        r = (lane < (NTHREADS / 32)) ? red[lane] : 0.f;
#pragma unroll
        for (int o = 16; o; o >>= 1) r += __shfl_down_sync(0xffffffffu, r, o);
    }
    return r;  // valid on thread 0
}

__device__ __forceinline__ double block_reduce_d(double v, double* red) {
    const int lane = threadIdx.x & 31;
    const int wid  = threadIdx.x >> 5;
#pragma unroll
    for (int o = 16; o; o >>= 1) v += __shfl_down_sync(0xffffffffu, v, o);
    if (lane == 0) red[wid] = v;
    __syncthreads();
    double r = 0.0;
    if (wid == 0) {
        r = (lane < (NTHREADS / 32)) ? red[lane] : 0.0;
#pragma unroll
        for (int o = 16; o; o >>= 1) r += __shfl_down_sync(0xffffffffu, r, o);
    }
    return r;  // valid on thread 0
}

// ---------------------------------------------------------------------------
// Persistent fused kernel, single wave of 148 CTAs:
//   CTAs [0,128): BCE + prob-reg on 2 batch rows (fp16 smem sigmoid cache),
//                 then join the rec work-steal pool.
//   CTAs [128,148): straight to the rec pool.
//   Rec: warp-granular stealing; one warp processes one edge (two 4 KB rows,
//        16 LDG.128 per lane in two 8-deep bursts). Next ticket is fetched
//        before computing so the atomic latency hides behind the loads.
//   Last CTA to finish combines partials and writes the scalar.
// ---------------------------------------------------------------------------
__global__ void __launch_bounds__(NTHREADS, 1)
mega_kernel(const float* __restrict__ logits,
            const float* __restrict__ targets,
            const float* __restrict__ params,
            float* __restrict__ out) {
    extern __shared__ __align__(16) char smem_raw[];
    __shared__ float  s_redf[32];
    __shared__ double s_redd[32];
    __shared__ unsigned s_tick;

    const int tid  = threadIdx.x;
    const int lane = tid & 31;

    double p_bce = 0.0, p_pr = 0.0;

    if (blockIdx.x < BCE_BLOCKS) {
        // ---------------- BCE + prob role ----------------
        __half* s0 = (__half*)smem_raw;
        __half* s1 = (__half*)smem_raw + N_LABELS;
        const int b = blockIdx.x * 2;
        const float4* __restrict__ l0 = (const float4*)(logits  + (size_t)b * N_LABELS);
        const float4* __restrict__ t0 = (const float4*)(targets + (size_t)b * N_LABELS);
        const float4* __restrict__ l1 = (const float4*)(logits  + (size_t)(b + 1) * N_LABELS);
        const float4* __restrict__ t1 = (const float4*)(targets + (size_t)(b + 1) * N_LABELS);
        __half2* s0v = (__half2*)s0;
        __half2* s1v = (__half2*)s1;

        float bce = 0.f;
        for (int i = tid; i < N_LABELS / 4; i += NTHREADS) {
            float4 la = l0[i], ta = t0[i];
            float4 lb = l1[i], tb = t1[i];
            float sg[8];
            const float xs[8] = {la.x, la.y, la.z, la.w, lb.x, lb.y, lb.z, lb.w};
            const float ts[8] = {ta.x, ta.y, ta.z, ta.w, tb.x, tb.y, tb.z, tb.w};
#pragma unroll
            for (int k = 0; k < 8; k++) {
                float x = xs[k];
                float e = __expf(-fabsf(x));
                float r = __frcp_rn(1.f + e);           // sigmoid(|x|)
                bce += fmaxf(x, 0.f) - __logf(r) - x * ts[k];
                sg[k] = (x >= 0.f) ? r : (1.f - r);
            }
            s0v[2 * i]     = __floats2half2_rn(sg[0], sg[1]);
            s0v[2 * i + 1] = __floats2half2_rn(sg[2], sg[3]);
            s1v[2 * i]     = __floats2half2_rn(sg[4], sg[5]);
            s1v[2 * i + 1] = __floats2half2_rn(sg[6], sg[7]);
        }
        __syncthreads();

        float pr = 0.f;
        for (int e = tid; e < N_EDGES; e += NTHREADS) {
            int2 pc = g_edge[e];
            float d0 = __half2float(s0[pc.y]) - __half2float(s0[pc.x]);
            float d1 = __half2float(s1[pc.y]) - __half2float(s1[pc.x]);
            pr += fmaxf(d0, 0.f) + fmaxf(d1, 0.f);
        }

        float tb2 = block_reduce_f(bce, s_redf);
        __syncthreads();
        float tp = block_reduce_f(pr, s_redf);
        p_bce = (double)tb2;
        p_pr  = (double)tp;
        __syncthreads();   // s_redf reused below by the rec reduction
    }

    // ---------------- rec role: warp-granular work stealing ----------------
    float acc = 0.f;
    unsigned cur = 0xffffffffu;
    if (lane == 0) cur = atomicAdd(&g_work, 1u);
    cur = __shfl_sync(0xffffffffu, cur, 0);
    while (cur < N_EDGES) {
        unsigned nxt = 0xffffffffu;
        if (lane == 0) nxt = atomicAdd(&g_work, 1u);   // prefetch ticket

        int2 pc = g_edge[cur];
        const float4* __restrict__ pa =
            (const float4*)(params + (size_t)pc.x * HIDDEN) + lane;
        const float4* __restrict__ pb =
            (const float4*)(params + (size_t)pc.y * HIDDEN) + lane;
#pragma unroll
        for (int h = 0; h < 2; h++) {
            float4 a0 = pa[h * 128 +  0], a1 = pa[h * 128 + 32];
            float4 a2 = pa[h * 128 + 64], a3 = pa[h * 128 + 96];
            float4 b0 = pb[h * 128 +  0], b1 = pb[h * 128 + 32];
            float4 b2 = pb[h * 128 + 64], b3 = pb[h * 128 + 96];
            float d;
            d = a0.x - b0.x; acc = fmaf(d, d, acc);
            d = a0.y - b0.y; acc = fmaf(d, d, acc);
            d = a0.z - b0.z; acc = fmaf(d, d, acc);
            d = a0.w - b0.w; acc = fmaf(d, d, acc);
            d = a1.x - b1.x; acc = fmaf(d, d, acc);
            d = a1.y - b1.y; acc = fmaf(d, d, acc);
            d = a1.z - b1.z; acc = fmaf(d, d, acc);
            d = a1.w - b1.w; acc = fmaf(d, d, acc);
            d = a2.x - b2.x; acc = fmaf(d, d, acc);
            d = a2.y - b2.y; acc = fmaf(d, d, acc);
            d = a2.z - b2.z; acc = fmaf(d, d, acc);
            d = a2.w - b2.w; acc = fmaf(d, d, acc);
            d = a3.x - b3.x; acc = fmaf(d, d, acc);
            d = a3.y - b3.y; acc = fmaf(d, d, acc);
            d = a3.z - b3.z; acc = fmaf(d, d, acc);
            d = a3.w - b3.w; acc = fmaf(d, d, acc);
        }
        cur = __shfl_sync(0xffffffffu, nxt, 0);
    }

    float tr = block_reduce_f(acc, s_redf);
    double p_rec = (double)tr;

    // ---------------- partials + ticket ----------------
    if (tid == 0) {
        g_part[blockIdx.x][0] = p_bce;
        g_part[blockIdx.x][1] = p_rec;
        g_part[blockIdx.x][2] = p_pr;
        __threadfence();
        s_tick = atomicAdd(&g_ticket, 1u);
    }
    __syncthreads();

    if (s_tick == GRID - 1) {
        double sb = 0.0, sr = 0.0, sp = 0.0;
        for (int i = tid; i < GRID; i += NTHREADS) {
            sb += g_part[i][0];
            sr += g_part[i][1];
            sp += g_part[i][2];
        }
        double tb2 = block_reduce_d(sb, s_redd);
        __syncthreads();
        double trr = block_reduce_d(sr, s_redd);
        __syncthreads();
        double tpp = block_reduce_d(sp, s_redd);
        if (tid == 0) {
            out[0] = (float)(tb2 / ((double)BATCH * (double)N_LABELS)
                             + 1e-4 * 0.5 * trr + 1e-4 * tpp);
        }
    }
}

// ---------------------------------------------------------------------------
// Launch. Inputs: logits, targets, params, parent_idx, child_idx. Output: f32.
// ---------------------------------------------------------------------------
extern "C" void kernel_launch(void* const* d_in, const int* in_sizes, int n_in,
                              void* d_out, int out_size) {
    const float* logits  = (const float*)d_in[0];
    const float* targets = (const float*)d_in[1];
    const float* params  = (const float*)d_in[2];
    const void*  par     = d_in[3];
    const void*  chi     = d_in[4];
    float* out = (float*)d_out;
    (void)in_sizes; (void)n_in; (void)out_size;

    cudaFuncSetAttribute(mega_kernel,
                         cudaFuncAttributeMaxDynamicSharedMemorySize, SMEM_BYTES);

    init_kernel<<<(N_EDGES + 255) / 256, 256>>>(par, chi);
    mega_kernel<<<GRID, NTHREADS, SMEM_BYTES>>>(logits, targets, params, out);
}